// round 6
// baseline (speedup 1.0000x reference)
#include <cuda_runtime.h>
#include <cstdint>

// VQ quantize via mma.sync tf32 (3xTF32 split = fp32-grade scores).
// 6 independent accumulator chains per warp to saturate the tensor pipe.
// x: [131072, 64] f32, embed: [64, 512] f32.
// Out f32: quantize (8388608) | diff (1) | embed_ind (131072).

#define DIMK 64
#define NCODE 512
#define NROWS (32 * 64 * 64)
#define NTOT (NROWS * DIMK)
#define TPB 256
#define M_TILE 256
#define NBLK (NROWS / M_TILE)   // 512
#define XS_STRIDE 68

// smem byte offsets
#define SM_XS 0                         // 256*68*4 = 69632
#define SM_B 69632                      // 131072 (half of B fragments)
#define SM_NRM (SM_B + 131072)          // 2048
#define SM_WIN (SM_NRM + 2048)          // 1024
#define SM_RED (SM_WIN + 1024)          // 1024
#define SM_BYTES (SM_RED + 1024)        // 204800

__device__ __align__(16) float4 g_Bfrag[64 * 8 * 32];   // [nc][kc][lane] = {bh0,bh1,bl0,bl1}
__device__ __align__(16) float g_embT[NCODE * DIMK];
__device__ float g_nrm[NCODE];
__device__ unsigned long long g_diff_acc;
__device__ unsigned int g_ticket;

__device__ __forceinline__ uint32_t tf32_hi(float f) {
    uint32_t r;
    asm("cvt.rna.tf32.f32 %0, %1;" : "=r"(r) : "f"(f));
    return r;
}
__device__ __forceinline__ void mma8(float* c, const uint32_t* a, uint32_t b0, uint32_t b1) {
    asm volatile(
        "mma.sync.aligned.m16n8k8.row.col.f32.tf32.tf32.f32 "
        "{%0,%1,%2,%3}, {%4,%5,%6,%7}, {%8,%9}, {%0,%1,%2,%3};"
        : "+f"(c[0]), "+f"(c[1]), "+f"(c[2]), "+f"(c[3])
        : "r"(a[0]), "r"(a[1]), "r"(a[2]), "r"(a[3]), "r"(b0), "r"(b1));
}

// ---- prep: codebook transpose, norms, B fragments in mma layout ----
__global__ void vq_prep(const float* __restrict__ embed) {
    int t = threadIdx.x;  // 512
    float nr = 0.f;
    for (int d = 0; d < DIMK; d++) {
        float e = embed[d * NCODE + t];
        g_embT[t * DIMK + d] = e;
        nr = fmaf(e, e, nr);
    }
    g_nrm[t] = nr;
    for (int i = t; i < 64 * 8 * 32; i += 512) {
        int lane = i & 31;
        int kc = (i >> 5) & 7;
        int nc = i >> 8;
        int gid = lane >> 2, tig = lane & 3;
        int n = nc * 8 + gid;
        int k0 = kc * 8 + tig;
        float v0 = -2.f * embed[k0 * NCODE + n];
        float v1 = -2.f * embed[(k0 + 4) * NCODE + n];
        uint32_t h0 = tf32_hi(v0), h1 = tf32_hi(v1);
        uint32_t l0 = tf32_hi(v0 - __uint_as_float(h0));
        uint32_t l1 = tf32_hi(v1 - __uint_as_float(h1));
        float4 f;
        f.x = __uint_as_float(h0);
        f.y = __uint_as_float(h1);
        f.z = __uint_as_float(l0);
        f.w = __uint_as_float(l1);
        g_Bfrag[i] = f;
    }
}

__global__ __launch_bounds__(TPB, 1)
void vq_mma_kernel(const float* __restrict__ x,
                   float* __restrict__ out,
                   int out_size) {
    extern __shared__ char smem[];
    float* xs = (float*)(smem + SM_XS);
    float4* Bsm = (float4*)(smem + SM_B);
    float* nsm = (float*)(smem + SM_NRM);
    int* WIN = (int*)(smem + SM_WIN);
    float* red = (float*)(smem + SM_RED);

    int tid = threadIdx.x, wid = tid >> 5, lane = tid & 31;
    int gid = lane >> 2, tig = lane & 3;
    int base_row = blockIdx.x * M_TILE;

    for (int i = tid; i < M_TILE * 16; i += TPB) {
        int r = i >> 4, c4 = i & 15;
        float4 v = ((const float4*)(x + (size_t)(base_row + r) * DIMK))[c4];
        float* dst = xs + r * XS_STRIDE + c4 * 4;
        dst[0] = v.x; dst[1] = v.y; dst[2] = v.z; dst[3] = v.w;
    }
    for (int i = tid; i < NCODE; i += TPB) nsm[i] = g_nrm[i];
    __syncthreads();

    // A fragments (tf32 hi/lo) in registers: 2 m16 tiles x 8 k-chunks
    int m0 = wid * 32;
    uint32_t Ah[2][8][4], Al[2][8][4];
#pragma unroll
    for (int t2 = 0; t2 < 2; t2++)
#pragma unroll
        for (int kc = 0; kc < 8; kc++) {
            int r0 = m0 + t2 * 16 + gid;
            int c0 = kc * 8 + tig;
            float f[4];
            f[0] = xs[r0 * XS_STRIDE + c0];
            f[1] = xs[(r0 + 8) * XS_STRIDE + c0];
            f[2] = xs[r0 * XS_STRIDE + c0 + 4];
            f[3] = xs[(r0 + 8) * XS_STRIDE + c0 + 4];
#pragma unroll
            for (int j = 0; j < 4; j++) {
                uint32_t h = tf32_hi(f[j]);
                Ah[t2][kc][j] = h;
                Al[t2][kc][j] = tf32_hi(f[j] - __uint_as_float(h));
            }
        }

    float best[4];
    int bi[4];
#pragma unroll
    for (int j = 0; j < 4; j++) { best[j] = __int_as_float(0x7f800000); bi[j] = 0; }

#pragma unroll 1
    for (int half = 0; half < 2; half++) {
        __syncthreads();
        const float4* src = g_Bfrag + half * 8192;
        for (int i = tid; i < 8192; i += TPB) Bsm[i] = src[i];
        __syncthreads();

#pragma unroll 1
        for (int nc = 0; nc < 32; nc++) {
            // 6 independent accumulator chains: {hh,lh,hl} x {tile0,tile1}
            float hh0[4] = {0, 0, 0, 0}, lh0[4] = {0, 0, 0, 0}, hl0[4] = {0, 0, 0, 0};
            float hh1[4] = {0, 0, 0, 0}, lh1[4] = {0, 0, 0, 0}, hl1[4] = {0, 0, 0, 0};
#pragma unroll
            for (int kc = 0; kc < 8; kc++) {
                float4 b = Bsm[(nc * 8 + kc) * 32 + lane];
                uint32_t bh0 = __float_as_uint(b.x), bh1 = __float_as_uint(b.y);
                uint32_t bl0 = __float_as_uint(b.z), bl1 = __float_as_uint(b.w);
                mma8(hh0, Ah[0][kc], bh0, bh1);
                mma8(hh1, Ah[1][kc], bh0, bh1);
                mma8(lh0, Al[0][kc], bh0, bh1);
                mma8(lh1, Al[1][kc], bh0, bh1);
                mma8(hl0, Ah[0][kc], bl0, bl1);
                mma8(hl1, Ah[1][kc], bl0, bl1);
            }
            int n0 = half * 256 + nc * 8;
            float2 nv = *(const float2*)(nsm + n0 + 2 * tig);
            int ca = n0 + 2 * tig, cb = ca + 1;
            float s;
            s = ((lh0[0] + hl0[0]) + hh0[0]) + nv.x; if (s < best[0]) { best[0] = s; bi[0] = ca; }
            s = ((lh0[1] + hl0[1]) + hh0[1]) + nv.y; if (s < best[0]) { best[0] = s; bi[0] = cb; }
            s = ((lh0[2] + hl0[2]) + hh0[2]) + nv.x; if (s < best[1]) { best[1] = s; bi[1] = ca; }
            s = ((lh0[3] + hl0[3]) + hh0[3]) + nv.y; if (s < best[1]) { best[1] = s; bi[1] = cb; }
            s = ((lh1[0] + hl1[0]) + hh1[0]) + nv.x; if (s < best[2]) { best[2] = s; bi[2] = ca; }
            s = ((lh1[1] + hl1[1]) + hh1[1]) + nv.y; if (s < best[2]) { best[2] = s; bi[2] = cb; }
            s = ((lh1[2] + hl1[2]) + hh1[2]) + nv.x; if (s < best[3]) { best[3] = s; bi[3] = ca; }
            s = ((lh1[3] + hl1[3]) + hh1[3]) + nv.y; if (s < best[3]) { best[3] = s; bi[3] = cb; }
        }
    }

    // reduce across the 4 lanes of each quad
#pragma unroll
    for (int j = 0; j < 4; j++) {
        float b = best[j];
        int ix = bi[j];
#pragma unroll
        for (int o = 1; o < 4; o <<= 1) {
            float ob = __shfl_xor_sync(0xffffffffu, b, o);
            int oi = __shfl_xor_sync(0xffffffffu, ix, o);
            if (ob < b || (ob == b && oi < ix)) { b = ob; ix = oi; }
        }
        if (tig == 0) WIN[m0 + j * 8 + gid] = ix;
    }
    __syncthreads();

    // phase 2: quantize writes + diff + ind (32 rows per warp)
    float dsum = 0.f;
    bool write_ind = (out_size >= NTOT + 1 + NROWS);
#pragma unroll 1
    for (int i = 0; i < 32; i++) {
        int r = wid * 32 + i;
        int bk = WIN[r];
        size_t n = (size_t)base_row + r;
        float2 ev = ((const float2*)(g_embT + bk * DIMK))[lane];
        float2 xv = ((const float2*)(x + n * DIMK))[lane];
        ((float2*)(out + n * DIMK))[lane] = ev;
        float dx = ev.x - xv.x, dy = ev.y - xv.y;
        dsum = fmaf(dx, dx, dsum);
        dsum = fmaf(dy, dy, dsum);
        if (lane == 0 && write_ind) out[NTOT + 1 + n] = (float)bk;
    }

    red[tid] = dsum;
    __syncthreads();
#pragma unroll
    for (int s = TPB / 2; s > 0; s >>= 1) {
        if (tid < s) red[tid] += red[tid + s];
        __syncthreads();
    }
    if (tid == 0) {
        unsigned long long q = (unsigned long long)((double)red[0] * 1048576.0 + 0.5);
        atomicAdd(&g_diff_acc, q);
        __threadfence();
        unsigned t = atomicAdd(&g_ticket, 1u);
        if (t == (unsigned)(NBLK - 1)) {
            unsigned long long tot = atomicExch(&g_diff_acc, 0ull);
            atomicExch(&g_ticket, 0u);
            if (out_size >= NTOT + 1)
                out[NTOT] = (float)((double)tot * (1.0 / 1048576.0) / (double)NTOT);
        }
    }
}

extern "C" void kernel_launch(void* const* d_in, const int* in_sizes, int n_in,
                              void* d_out, int out_size) {
    const float* x = (const float*)d_in[0];
    const float* embed = (const float*)d_in[1];
    float* out = (float*)d_out;

    cudaFuncSetAttribute(vq_mma_kernel,
                         cudaFuncAttributeMaxDynamicSharedMemorySize, SM_BYTES);

    vq_prep<<<1, NCODE>>>(embed);
    vq_mma_kernel<<<NBLK, TPB, SM_BYTES>>>(x, out, out_size);
}

// round 8
// speedup vs baseline: 1.0730x; 1.0730x over previous
#include <cuda_runtime.h>
#include <cstdint>

// VQ quantize via mma.sync tf32 (3xTF32 split = fp32-grade scores).
// R6 numerics EXACTLY (known-pass). Scheduling only:
//  - register double-buffer of B fragments (LDS prefetch hides latency)
//  - cp.async quarter-pipelined B staging (no half-boundary stalls)
// x: [131072, 64] f32, embed: [64, 512] f32.
// Out f32: quantize (8388608) | diff (1) | embed_ind (131072).

#define DIMK 64
#define NCODE 512
#define NROWS (32 * 64 * 64)
#define NTOT (NROWS * DIMK)
#define TPB 256
#define M_TILE 256
#define NBLK (NROWS / M_TILE)   // 512
#define XS_STRIDE 68
#define QF4 4096                 // float4 per 64KB quarter (16 nc-blocks)

#define SM_XS 0                          // 69632
#define SM_B0 69632                      // 65536 (quarter ping)
#define SM_B1 (SM_B0 + 65536)            // 65536 (quarter pong)
#define SM_NRM (SM_B1 + 65536)           // 2048
#define SM_WIN (SM_NRM + 2048)           // 1024
#define SM_RED (SM_WIN + 1024)           // 1024
#define SM_BYTES (SM_RED + 1024)         // 204800

__device__ __align__(16) float4 g_Bfrag[64 * 8 * 32];   // [nc][kc][lane] = {bh0,bh1,bl0,bl1}
__device__ __align__(16) float g_embT[NCODE * DIMK];
__device__ float g_nrm[NCODE];
__device__ unsigned long long g_diff_acc;
__device__ unsigned int g_ticket;

__device__ __forceinline__ uint32_t smem_u32(const void* p) {
    uint32_t a;
    asm("{ .reg .u64 t; cvta.to.shared.u64 t, %1; cvt.u32.u64 %0, t; }" : "=r"(a) : "l"(p));
    return a;
}
__device__ __forceinline__ uint32_t tf32_hi(float f) {
    uint32_t r;
    asm("cvt.rna.tf32.f32 %0, %1;" : "=r"(r) : "f"(f));
    return r;
}
__device__ __forceinline__ void mma8(float* c, const uint32_t* a, uint32_t b0, uint32_t b1) {
    asm volatile(
        "mma.sync.aligned.m16n8k8.row.col.f32.tf32.tf32.f32 "
        "{%0,%1,%2,%3}, {%4,%5,%6,%7}, {%8,%9}, {%0,%1,%2,%3};"
        : "+f"(c[0]), "+f"(c[1]), "+f"(c[2]), "+f"(c[3])
        : "r"(a[0]), "r"(a[1]), "r"(a[2]), "r"(a[3]), "r"(b0), "r"(b1));
}
__device__ __forceinline__ void cp16(uint32_t s, const void* g) {
    asm volatile("cp.async.cg.shared.global [%0], [%1], 16;" :: "r"(s), "l"(g) : "memory");
}
#define CP_COMMIT() asm volatile("cp.async.commit_group;" ::: "memory")
#define CP_WAIT(n)  asm volatile("cp.async.wait_group %0;" :: "n"(n) : "memory")

__global__ void vq_prep(const float* __restrict__ embed) {
    int t = threadIdx.x;  // 512
    float nr = 0.f;
    for (int d = 0; d < DIMK; d++) {
        float e = embed[d * NCODE + t];
        g_embT[t * DIMK + d] = e;
        nr = fmaf(e, e, nr);
    }
    g_nrm[t] = nr;
    for (int i = t; i < 64 * 8 * 32; i += 512) {
        int lane = i & 31;
        int kc = (i >> 5) & 7;
        int nc = i >> 8;
        int gid = lane >> 2, tig = lane & 3;
        int n = nc * 8 + gid;
        int k0 = kc * 8 + tig;
        float v0 = -2.f * embed[k0 * NCODE + n];
        float v1 = -2.f * embed[(k0 + 4) * NCODE + n];
        uint32_t h0 = tf32_hi(v0), h1 = tf32_hi(v1);
        uint32_t l0 = tf32_hi(v0 - __uint_as_float(h0));
        uint32_t l1 = tf32_hi(v1 - __uint_as_float(h1));
        float4 f;
        f.x = __uint_as_float(h0);
        f.y = __uint_as_float(h1);
        f.z = __uint_as_float(l0);
        f.w = __uint_as_float(l1);
        g_Bfrag[i] = f;
    }
}

__global__ __launch_bounds__(TPB, 1)
void vq_mma_kernel(const float* __restrict__ x,
                   float* __restrict__ out,
                   int out_size) {
    extern __shared__ char smem[];
    float* xs = (float*)(smem + SM_XS);
    float* nsm = (float*)(smem + SM_NRM);
    int* WIN = (int*)(smem + SM_WIN);
    float* red = (float*)(smem + SM_RED);

    int tid = threadIdx.x, wid = tid >> 5, lane = tid & 31;
    int gid = lane >> 2, tig = lane & 3;
    int base_row = blockIdx.x * M_TILE;

    // kick off async load of B quarter 0 into ping
    {
        uint32_t dst = smem_u32(smem + SM_B0) + tid * 16;
        const float4* src = g_Bfrag + tid;
#pragma unroll
        for (int i = 0; i < QF4 / TPB; i++)
            cp16(dst + i * TPB * 16, src + i * TPB);
        CP_COMMIT();
    }

    // x tile -> padded smem (overlaps with cp.async above)
    for (int i = tid; i < M_TILE * 16; i += TPB) {
        int r = i >> 4, c4 = i & 15;
        float4 v = ((const float4*)(x + (size_t)(base_row + r) * DIMK))[c4];
        float* dst = xs + r * XS_STRIDE + c4 * 4;
        dst[0] = v.x; dst[1] = v.y; dst[2] = v.z; dst[3] = v.w;
    }
    for (int i = tid; i < NCODE; i += TPB) nsm[i] = g_nrm[i];
    __syncthreads();

    // A fragments (tf32 hi/lo): 2 m16 tiles x 8 k-chunks
    int m0 = wid * 32;
    uint32_t Ah[2][8][4], Al[2][8][4];
#pragma unroll
    for (int t2 = 0; t2 < 2; t2++)
#pragma unroll
        for (int kc = 0; kc < 8; kc++) {
            int r0 = m0 + t2 * 16 + gid;
            int c0 = kc * 8 + tig;
            float f[4];
            f[0] = xs[r0 * XS_STRIDE + c0];
            f[1] = xs[(r0 + 8) * XS_STRIDE + c0];
            f[2] = xs[r0 * XS_STRIDE + c0 + 4];
            f[3] = xs[(r0 + 8) * XS_STRIDE + c0 + 4];
#pragma unroll
            for (int j = 0; j < 4; j++) {
                uint32_t h = tf32_hi(f[j]);
                Ah[t2][kc][j] = h;
                Al[t2][kc][j] = tf32_hi(f[j] - __uint_as_float(h));
            }
        }

    float best[4];
    int bi[4];
#pragma unroll
    for (int j = 0; j < 4; j++) { best[j] = __int_as_float(0x7f800000); bi[j] = 0; }

#pragma unroll 1
    for (int q = 0; q < 4; q++) {
        // issue next quarter into the other buffer (readers of it finished last iter)
        if (q < 3) {
            uint32_t dst = smem_u32(smem + ((q & 1) ? SM_B0 : SM_B1)) + tid * 16;
            const float4* src = g_Bfrag + (q + 1) * QF4 + tid;
#pragma unroll
            for (int i = 0; i < QF4 / TPB; i++)
                cp16(dst + i * TPB * 16, src + i * TPB);
            CP_COMMIT();
            CP_WAIT(1);   // quarter q's group complete
        } else {
            CP_WAIT(0);
        }
        __syncthreads();

        const float4* Bq = (const float4*)(smem + ((q & 1) ? SM_B1 : SM_B0));

        // prime register B buffer with nc_local=0
        float4 bA[8], bB[8];
#pragma unroll
        for (int kc = 0; kc < 8; kc++) bA[kc] = Bq[kc * 32 + lane];

#pragma unroll 2
        for (int ncl = 0; ncl < 16; ncl++) {
            float4* bcur = (ncl & 1) ? bB : bA;
            float4* bnxt = (ncl & 1) ? bA : bB;
            int nn = (ncl < 15) ? ncl + 1 : 15;
#pragma unroll
            for (int kc = 0; kc < 8; kc++) bnxt[kc] = Bq[(nn * 8 + kc) * 32 + lane];

            // R6-exact numerics: accumulators from 0, norm added last
            float hh0[4] = {0, 0, 0, 0}, lh0[4] = {0, 0, 0, 0}, hl0[4] = {0, 0, 0, 0};
            float hh1[4] = {0, 0, 0, 0}, lh1[4] = {0, 0, 0, 0}, hl1[4] = {0, 0, 0, 0};
#pragma unroll
            for (int kc = 0; kc < 8; kc++) {
                uint32_t bh0 = __float_as_uint(bcur[kc].x), bh1 = __float_as_uint(bcur[kc].y);
                uint32_t bl0 = __float_as_uint(bcur[kc].z), bl1 = __float_as_uint(bcur[kc].w);
                mma8(hh0, Ah[0][kc], bh0, bh1);
                mma8(hh1, Ah[1][kc], bh0, bh1);
                mma8(lh0, Al[0][kc], bh0, bh1);
                mma8(lh1, Al[1][kc], bh0, bh1);
                mma8(hl0, Ah[0][kc], bl0, bl1);
                mma8(hl1, Ah[1][kc], bl0, bl1);
            }
            int n0 = (q * 16 + ncl) * 8;
            float2 nv = *(const float2*)(nsm + n0 + 2 * tig);
            int ca = n0 + 2 * tig, cb = ca + 1;
            float s;
            s = ((lh0[0] + hl0[0]) + hh0[0]) + nv.x; if (s < best[0]) { best[0] = s; bi[0] = ca; }
            s = ((lh0[1] + hl0[1]) + hh0[1]) + nv.y; if (s < best[0]) { best[0] = s; bi[0] = cb; }
            s = ((lh0[2] + hl0[2]) + hh0[2]) + nv.x; if (s < best[1]) { best[1] = s; bi[1] = ca; }
            s = ((lh0[3] + hl0[3]) + hh0[3]) + nv.y; if (s < best[1]) { best[1] = s; bi[1] = cb; }
            s = ((lh1[0] + hl1[0]) + hh1[0]) + nv.x; if (s < best[2]) { best[2] = s; bi[2] = ca; }
            s = ((lh1[1] + hl1[1]) + hh1[1]) + nv.y; if (s < best[2]) { best[2] = s; bi[2] = cb; }
            s = ((lh1[2] + hl1[2]) + hh1[2]) + nv.x; if (s < best[3]) { best[3] = s; bi[3] = ca; }
            s = ((lh1[3] + hl1[3]) + hh1[3]) + nv.y; if (s < best[3]) { best[3] = s; bi[3] = cb; }
        }
        __syncthreads();   // done reading Bq before it is overwritten next iter
    }

    // reduce across the 4 lanes of each quad
#pragma unroll
    for (int j = 0; j < 4; j++) {
        float b = best[j];
        int ix = bi[j];
#pragma unroll
        for (int o = 1; o < 4; o <<= 1) {
            float ob = __shfl_xor_sync(0xffffffffu, b, o);
            int oi = __shfl_xor_sync(0xffffffffu, ix, o);
            if (ob < b || (ob == b && oi < ix)) { b = ob; ix = oi; }
        }
        if (tig == 0) WIN[m0 + j * 8 + gid] = ix;
    }
    __syncthreads();

    // phase 2: quantize writes + diff + ind (32 rows per warp)
    float dsum = 0.f;
    bool write_ind = (out_size >= NTOT + 1 + NROWS);
#pragma unroll 1
    for (int i = 0; i < 32; i++) {
        int r = wid * 32 + i;
        int bk = WIN[r];
        size_t n = (size_t)base_row + r;
        float2 ev = ((const float2*)(g_embT + bk * DIMK))[lane];
        float2 xv = ((const float2*)(x + n * DIMK))[lane];
        ((float2*)(out + n * DIMK))[lane] = ev;
        float dx = ev.x - xv.x, dy = ev.y - xv.y;
        dsum = fmaf(dx, dx, dsum);
        dsum = fmaf(dy, dy, dsum);
        if (lane == 0 && write_ind) out[NTOT + 1 + n] = (float)bk;
    }

    red[tid] = dsum;
    __syncthreads();
#pragma unroll
    for (int s = TPB / 2; s > 0; s >>= 1) {
        if (tid < s) red[tid] += red[tid + s];
        __syncthreads();
    }
    if (tid == 0) {
        unsigned long long q2 = (unsigned long long)((double)red[0] * 1048576.0 + 0.5);
        atomicAdd(&g_diff_acc, q2);
        __threadfence();
        unsigned t = atomicAdd(&g_ticket, 1u);
        if (t == (unsigned)(NBLK - 1)) {
            unsigned long long tot = atomicExch(&g_diff_acc, 0ull);
            atomicExch(&g_ticket, 0u);
            if (out_size >= NTOT + 1)
                out[NTOT] = (float)((double)tot * (1.0 / 1048576.0) / (double)NTOT);
        }
    }
}

extern "C" void kernel_launch(void* const* d_in, const int* in_sizes, int n_in,
                              void* d_out, int out_size) {
    const float* x = (const float*)d_in[0];
    const float* embed = (const float*)d_in[1];
    float* out = (float*)d_out;

    cudaFuncSetAttribute(vq_mma_kernel,
                         cudaFuncAttributeMaxDynamicSharedMemorySize, SM_BYTES);

    vq_prep<<<1, NCODE>>>(embed);
    vq_mma_kernel<<<NBLK, TPB, SM_BYTES>>>(x, out, out_size);
}

// round 10
// speedup vs baseline: 1.1673x; 1.0879x over previous
#include <cuda_runtime.h>
#include <cstdint>

// VQ quantize via mma.sync tf32 (3xTF32 split = fp32-grade scores).
// 16 warps/CTA (4 warps/SMSP), one m16 tile per warp.
// B fragments (256KB) streamed through two 64KB smem quarters (cp.async).
// A fragments built by direct LDG (no x smem staging).
// Score arithmetic bit-identical to R8. Out: quantize | diff | ind.

#define DIMK 64
#define NCODE 512
#define NROWS (32 * 64 * 64)
#define NTOT (NROWS * DIMK)
#define TPB 512
#define M_TILE 256
#define NBLK (NROWS / M_TILE)   // 512
#define QF4 4096                 // float4 per 64KB quarter (16 nc-blocks)

#define SM_B0 0                          // 65536
#define SM_B1 65536                      // 65536
#define SM_NRM 131072                    // 2048
#define SM_WIN (SM_NRM + 2048)           // 1024
#define SM_RED (SM_WIN + 1024)           // 2048
#define SM_BYTES (SM_RED + 2048)         // 136192

__device__ __align__(16) float4 g_Bfrag[64 * 8 * 32];   // [nc][kc][lane] = {bh0,bh1,bl0,bl1}
__device__ __align__(16) float g_embT[NCODE * DIMK];
__device__ float g_nrm[NCODE];
__device__ unsigned long long g_diff_acc;
__device__ unsigned int g_ticket;

__device__ __forceinline__ uint32_t smem_u32(const void* p) {
    uint32_t a;
    asm("{ .reg .u64 t; cvta.to.shared.u64 t, %1; cvt.u32.u64 %0, t; }" : "=r"(a) : "l"(p));
    return a;
}
__device__ __forceinline__ uint32_t tf32_hi(float f) {
    uint32_t r;
    asm("cvt.rna.tf32.f32 %0, %1;" : "=r"(r) : "f"(f));
    return r;
}
__device__ __forceinline__ void mma8(float* c, const uint32_t* a, uint32_t b0, uint32_t b1) {
    asm volatile(
        "mma.sync.aligned.m16n8k8.row.col.f32.tf32.tf32.f32 "
        "{%0,%1,%2,%3}, {%4,%5,%6,%7}, {%8,%9}, {%0,%1,%2,%3};"
        : "+f"(c[0]), "+f"(c[1]), "+f"(c[2]), "+f"(c[3])
        : "r"(a[0]), "r"(a[1]), "r"(a[2]), "r"(a[3]), "r"(b0), "r"(b1));
}
__device__ __forceinline__ void cp16(uint32_t s, const void* g) {
    asm volatile("cp.async.cg.shared.global [%0], [%1], 16;" :: "r"(s), "l"(g) : "memory");
}
#define CP_COMMIT() asm volatile("cp.async.commit_group;" ::: "memory")
#define CP_WAIT1()  asm volatile("cp.async.wait_group 1;" ::: "memory")
#define CP_WAIT0()  asm volatile("cp.async.wait_group 0;" ::: "memory")

__global__ void vq_prep(const float* __restrict__ embed) {
    int t = threadIdx.x;  // 512
    float nr = 0.f;
    for (int d = 0; d < DIMK; d++) {
        float e = embed[d * NCODE + t];
        g_embT[t * DIMK + d] = e;
        nr = fmaf(e, e, nr);
    }
    g_nrm[t] = nr;
    for (int i = t; i < 64 * 8 * 32; i += 512) {
        int lane = i & 31;
        int kc = (i >> 5) & 7;
        int nc = i >> 8;
        int gid = lane >> 2, tig = lane & 3;
        int n = nc * 8 + gid;
        int k0 = kc * 8 + tig;
        float v0 = -2.f * embed[k0 * NCODE + n];
        float v1 = -2.f * embed[(k0 + 4) * NCODE + n];
        uint32_t h0 = tf32_hi(v0), h1 = tf32_hi(v1);
        uint32_t l0 = tf32_hi(v0 - __uint_as_float(h0));
        uint32_t l1 = tf32_hi(v1 - __uint_as_float(h1));
        float4 f;
        f.x = __uint_as_float(h0);
        f.y = __uint_as_float(h1);
        f.z = __uint_as_float(l0);
        f.w = __uint_as_float(l1);
        g_Bfrag[i] = f;
    }
}

__global__ __launch_bounds__(TPB, 1)
void vq_mma_kernel(const float* __restrict__ x,
                   float* __restrict__ out,
                   int out_size) {
    extern __shared__ char smem[];
    float* nsm = (float*)(smem + SM_NRM);
    int* WIN = (int*)(smem + SM_WIN);
    float* red = (float*)(smem + SM_RED);

    int tid = threadIdx.x, wid = tid >> 5, lane = tid & 31;
    int gid = lane >> 2, tig = lane & 3;
    int base_row = blockIdx.x * M_TILE;

    // kick off async load of B quarter 0 into ping
    {
        uint32_t dst = smem_u32(smem + SM_B0) + tid * 16;
        const float4* src = g_Bfrag + tid;
#pragma unroll
        for (int i = 0; i < QF4 / TPB; i++)
            cp16(dst + i * TPB * 16, src + i * TPB);
        CP_COMMIT();
    }

    for (int i = tid; i < NCODE; i += TPB) nsm[i] = g_nrm[i];

    // A fragments (tf32 hi/lo): ONE m16 tile per warp, direct from gmem.
    // Overlaps with the cp.async above.
    int m0 = wid * 16;
    uint32_t Ah[8][4], Al[8][4];
    {
        const float* xr0 = x + (size_t)(base_row + m0 + gid) * DIMK;
        const float* xr8 = xr0 + 8 * DIMK;
#pragma unroll
        for (int kc = 0; kc < 8; kc++) {
            int c0 = kc * 8 + tig;
            float f[4];
            f[0] = __ldg(xr0 + c0);
            f[1] = __ldg(xr8 + c0);
            f[2] = __ldg(xr0 + c0 + 4);
            f[3] = __ldg(xr8 + c0 + 4);
#pragma unroll
            for (int j = 0; j < 4; j++) {
                uint32_t h = tf32_hi(f[j]);
                Ah[kc][j] = h;
                Al[kc][j] = tf32_hi(f[j] - __uint_as_float(h));
            }
        }
    }

    float best[2];
    int bi[2];
    best[0] = best[1] = __int_as_float(0x7f800000);
    bi[0] = bi[1] = 0;

#pragma unroll 1
    for (int q = 0; q < 4; q++) {
        if (q < 3) {
            // readers of the other buffer finished last iter (trailing syncthreads)
            uint32_t dst = smem_u32(smem + ((q & 1) ? SM_B0 : SM_B1)) + tid * 16;
            const float4* src = g_Bfrag + (q + 1) * QF4 + tid;
#pragma unroll
            for (int i = 0; i < QF4 / TPB; i++)
                cp16(dst + i * TPB * 16, src + i * TPB);
            CP_COMMIT();
            CP_WAIT1();   // quarter q's group complete
        } else {
            CP_WAIT0();
        }
        __syncthreads();

        const float4* Bq = (const float4*)(smem + ((q & 1) ? SM_B1 : SM_B0));

#pragma unroll 2
        for (int ncl = 0; ncl < 16; ncl++) {
            float4 b[8];
#pragma unroll
            for (int kc = 0; kc < 8; kc++) b[kc] = Bq[(ncl * 8 + kc) * 32 + lane];

            // bit-identical score arithmetic to R8 (acc from 0, norm last)
            float hh[4] = {0, 0, 0, 0}, lh[4] = {0, 0, 0, 0}, hl[4] = {0, 0, 0, 0};
#pragma unroll
            for (int kc = 0; kc < 8; kc++) {
                uint32_t bh0 = __float_as_uint(b[kc].x), bh1 = __float_as_uint(b[kc].y);
                uint32_t bl0 = __float_as_uint(b[kc].z), bl1 = __float_as_uint(b[kc].w);
                mma8(hh, Ah[kc], bh0, bh1);
                mma8(lh, Al[kc], bh0, bh1);
                mma8(hl, Ah[kc], bl0, bl1);
            }
            int n0 = (q * 16 + ncl) * 8;
            float2 nv = *(const float2*)(nsm + n0 + 2 * tig);
            int ca = n0 + 2 * tig, cb = ca + 1;
            float s;
            s = ((lh[0] + hl[0]) + hh[0]) + nv.x; if (s < best[0]) { best[0] = s; bi[0] = ca; }
            s = ((lh[1] + hl[1]) + hh[1]) + nv.y; if (s < best[0]) { best[0] = s; bi[0] = cb; }
            s = ((lh[2] + hl[2]) + hh[2]) + nv.x; if (s < best[1]) { best[1] = s; bi[1] = ca; }
            s = ((lh[3] + hl[3]) + hh[3]) + nv.y; if (s < best[1]) { best[1] = s; bi[1] = cb; }
        }
        __syncthreads();   // done reading Bq before overwrite next iter
    }

    // reduce across the 4 lanes of each quad (j=0: row gid, j=1: row gid+8)
#pragma unroll
    for (int j = 0; j < 2; j++) {
        float b = best[j];
        int ix = bi[j];
#pragma unroll
        for (int o = 1; o < 4; o <<= 1) {
            float ob = __shfl_xor_sync(0xffffffffu, b, o);
            int oi = __shfl_xor_sync(0xffffffffu, ix, o);
            if (ob < b || (ob == b && oi < ix)) { b = ob; ix = oi; }
        }
        if (tig == 0) WIN[m0 + j * 8 + gid] = ix;
    }
    __syncthreads();

    // phase 2: quantize writes + diff + ind (16 rows per warp)
    float dsum = 0.f;
    bool write_ind = (out_size >= NTOT + 1 + NROWS);
#pragma unroll 1
    for (int i = 0; i < 16; i++) {
        int r = wid * 16 + i;
        int bk = WIN[r];
        size_t n = (size_t)base_row + r;
        float2 ev = ((const float2*)(g_embT + bk * DIMK))[lane];
        float2 xv = ((const float2*)(x + n * DIMK))[lane];
        ((float2*)(out + n * DIMK))[lane] = ev;
        float dx = ev.x - xv.x, dy = ev.y - xv.y;
        dsum = fmaf(dx, dx, dsum);
        dsum = fmaf(dy, dy, dsum);
        if (lane == 0 && write_ind) out[NTOT + 1 + n] = (float)bk;
    }

    red[tid] = dsum;
    __syncthreads();
#pragma unroll
    for (int s = TPB / 2; s > 0; s >>= 1) {
        if (tid < s) red[tid] += red[tid + s];
        __syncthreads();
    }
    if (tid == 0) {
        unsigned long long q2 = (unsigned long long)((double)red[0] * 1048576.0 + 0.5);
        atomicAdd(&g_diff_acc, q2);
        __threadfence();
        unsigned t = atomicAdd(&g_ticket, 1u);
        if (t == (unsigned)(NBLK - 1)) {
            unsigned long long tot = atomicExch(&g_diff_acc, 0ull);
            atomicExch(&g_ticket, 0u);
            if (out_size >= NTOT + 1)
                out[NTOT] = (float)((double)tot * (1.0 / 1048576.0) / (double)NTOT);
        }
    }
}

extern "C" void kernel_launch(void* const* d_in, const int* in_sizes, int n_in,
                              void* d_out, int out_size) {
    const float* x = (const float*)d_in[0];
    const float* embed = (const float*)d_in[1];
    float* out = (float*)d_out;

    cudaFuncSetAttribute(vq_mma_kernel,
                         cudaFuncAttributeMaxDynamicSharedMemorySize, SM_BYTES);

    vq_prep<<<1, NCODE>>>(embed);
    vq_mma_kernel<<<NBLK, TPB, SM_BYTES>>>(x, out, out_size);
}

// round 11
// speedup vs baseline: 1.3802x; 1.1825x over previous
#include <cuda_runtime.h>
#include <cstdint>

// VQ quantize via mma.sync tf32 (3xTF32 split = fp32-grade scores).
// TPB=256 / M_TILE=128 / 2 CTAs per SM for cross-CTA phase overlap.
// B fragments (256KB) streamed through two 32KB smem chunks (cp.async).
// Score arithmetic bit-identical to R8/R10. Out: quantize | diff | ind.

#define DIMK 64
#define NCODE 512
#define NROWS (32 * 64 * 64)
#define NTOT (NROWS * DIMK)
#define TPB 256
#define M_TILE 128
#define NBLK (NROWS / M_TILE)   // 1024
#define CF4 2048                 // float4 per 32KB chunk (8 nc-blocks)

#define SM_B0 0                          // 32768
#define SM_B1 32768                      // 32768
#define SM_NRM 65536                     // 2048
#define SM_WIN (SM_NRM + 2048)           // 512
#define SM_RED (SM_WIN + 512)            // 1024
#define SM_BYTES (SM_RED + 1024)         // 69120

__device__ __align__(16) float4 g_Bfrag[64 * 8 * 32];   // [nc][kc][lane] = {bh0,bh1,bl0,bl1}
__device__ __align__(16) float g_embT[NCODE * DIMK];
__device__ float g_nrm[NCODE];
__device__ unsigned long long g_diff_acc;
__device__ unsigned int g_ticket;

__device__ __forceinline__ uint32_t smem_u32(const void* p) {
    uint32_t a;
    asm("{ .reg .u64 t; cvta.to.shared.u64 t, %1; cvt.u32.u64 %0, t; }" : "=r"(a) : "l"(p));
    return a;
}
__device__ __forceinline__ uint32_t tf32_hi(float f) {
    uint32_t r;
    asm("cvt.rna.tf32.f32 %0, %1;" : "=r"(r) : "f"(f));
    return r;
}
__device__ __forceinline__ void mma8(float* c, const uint32_t* a, uint32_t b0, uint32_t b1) {
    asm volatile(
        "mma.sync.aligned.m16n8k8.row.col.f32.tf32.tf32.f32 "
        "{%0,%1,%2,%3}, {%4,%5,%6,%7}, {%8,%9}, {%0,%1,%2,%3};"
        : "+f"(c[0]), "+f"(c[1]), "+f"(c[2]), "+f"(c[3])
        : "r"(a[0]), "r"(a[1]), "r"(a[2]), "r"(a[3]), "r"(b0), "r"(b1));
}
__device__ __forceinline__ void cp16(uint32_t s, const void* g) {
    asm volatile("cp.async.cg.shared.global [%0], [%1], 16;" :: "r"(s), "l"(g) : "memory");
}
#define CP_COMMIT() asm volatile("cp.async.commit_group;" ::: "memory")
#define CP_WAIT1()  asm volatile("cp.async.wait_group 1;" ::: "memory")
#define CP_WAIT0()  asm volatile("cp.async.wait_group 0;" ::: "memory")

__global__ void vq_prep(const float* __restrict__ embed) {
    int t = threadIdx.x;  // 512
    float nr = 0.f;
    for (int d = 0; d < DIMK; d++) {
        float e = embed[d * NCODE + t];
        g_embT[t * DIMK + d] = e;
        nr = fmaf(e, e, nr);
    }
    g_nrm[t] = nr;
    for (int i = t; i < 64 * 8 * 32; i += 512) {
        int lane = i & 31;
        int kc = (i >> 5) & 7;
        int nc = i >> 8;
        int gid = lane >> 2, tig = lane & 3;
        int n = nc * 8 + gid;
        int k0 = kc * 8 + tig;
        float v0 = -2.f * embed[k0 * NCODE + n];
        float v1 = -2.f * embed[(k0 + 4) * NCODE + n];
        uint32_t h0 = tf32_hi(v0), h1 = tf32_hi(v1);
        uint32_t l0 = tf32_hi(v0 - __uint_as_float(h0));
        uint32_t l1 = tf32_hi(v1 - __uint_as_float(h1));
        float4 f;
        f.x = __uint_as_float(h0);
        f.y = __uint_as_float(h1);
        f.z = __uint_as_float(l0);
        f.w = __uint_as_float(l1);
        g_Bfrag[i] = f;
    }
}

__global__ __launch_bounds__(TPB, 2)
void vq_mma_kernel(const float* __restrict__ x,
                   float* __restrict__ out,
                   int out_size) {
    extern __shared__ char smem[];
    float* nsm = (float*)(smem + SM_NRM);
    int* WIN = (int*)(smem + SM_WIN);
    float* red = (float*)(smem + SM_RED);

    int tid = threadIdx.x, wid = tid >> 5, lane = tid & 31;
    int gid = lane >> 2, tig = lane & 3;
    int base_row = blockIdx.x * M_TILE;

    // kick off async load of B chunk 0 into ping
    {
        uint32_t dst = smem_u32(smem + SM_B0) + tid * 16;
        const float4* src = g_Bfrag + tid;
#pragma unroll
        for (int i = 0; i < CF4 / TPB; i++)
            cp16(dst + i * TPB * 16, src + i * TPB);
        CP_COMMIT();
    }

    for (int i = tid; i < NCODE; i += TPB) nsm[i] = g_nrm[i];

    // A fragments (tf32 hi/lo): ONE m16 tile per warp, direct from gmem.
    int m0 = wid * 16;
    uint32_t Ah[8][4], Al[8][4];
    {
        const float* xr0 = x + (size_t)(base_row + m0 + gid) * DIMK;
        const float* xr8 = xr0 + 8 * DIMK;
#pragma unroll
        for (int kc = 0; kc < 8; kc++) {
            int c0 = kc * 8 + tig;
            float f[4];
            f[0] = __ldg(xr0 + c0);
            f[1] = __ldg(xr8 + c0);
            f[2] = __ldg(xr0 + c0 + 4);
            f[3] = __ldg(xr8 + c0 + 4);
#pragma unroll
            for (int j = 0; j < 4; j++) {
                uint32_t h = tf32_hi(f[j]);
                Ah[kc][j] = h;
                Al[kc][j] = tf32_hi(f[j] - __uint_as_float(h));
            }
        }
    }

    float best[2];
    int bi[2];
    best[0] = best[1] = __int_as_float(0x7f800000);
    bi[0] = bi[1] = 0;

#pragma unroll 1
    for (int c = 0; c < 8; c++) {
        if (c < 7) {
            uint32_t dst = smem_u32(smem + ((c & 1) ? SM_B0 : SM_B1)) + tid * 16;
            const float4* src = g_Bfrag + (c + 1) * CF4 + tid;
#pragma unroll
            for (int i = 0; i < CF4 / TPB; i++)
                cp16(dst + i * TPB * 16, src + i * TPB);
            CP_COMMIT();
            CP_WAIT1();   // chunk c's group complete
        } else {
            CP_WAIT0();
        }
        __syncthreads();

        const float4* Bq = (const float4*)(smem + ((c & 1) ? SM_B1 : SM_B0));

#pragma unroll 2
        for (int ncl = 0; ncl < 8; ncl++) {
            float4 b[8];
#pragma unroll
            for (int kc = 0; kc < 8; kc++) b[kc] = Bq[(ncl * 8 + kc) * 32 + lane];

            // bit-identical score arithmetic to R8 (acc from 0, norm last)
            float hh[4] = {0, 0, 0, 0}, lh[4] = {0, 0, 0, 0}, hl[4] = {0, 0, 0, 0};
#pragma unroll
            for (int kc = 0; kc < 8; kc++) {
                uint32_t bh0 = __float_as_uint(b[kc].x), bh1 = __float_as_uint(b[kc].y);
                uint32_t bl0 = __float_as_uint(b[kc].z), bl1 = __float_as_uint(b[kc].w);
                mma8(hh, Ah[kc], bh0, bh1);
                mma8(lh, Al[kc], bh0, bh1);
                mma8(hl, Ah[kc], bl0, bl1);
            }
            int n0 = (c * 8 + ncl) * 8;
            float2 nv = *(const float2*)(nsm + n0 + 2 * tig);
            int ca = n0 + 2 * tig, cb = ca + 1;
            float s;
            s = ((lh[0] + hl[0]) + hh[0]) + nv.x; if (s < best[0]) { best[0] = s; bi[0] = ca; }
            s = ((lh[1] + hl[1]) + hh[1]) + nv.y; if (s < best[0]) { best[0] = s; bi[0] = cb; }
            s = ((lh[2] + hl[2]) + hh[2]) + nv.x; if (s < best[1]) { best[1] = s; bi[1] = ca; }
            s = ((lh[3] + hl[3]) + hh[3]) + nv.y; if (s < best[1]) { best[1] = s; bi[1] = cb; }
        }
        __syncthreads();   // done reading Bq before overwrite next iter
    }

    // reduce across the 4 lanes of each quad (j=0: row gid, j=1: row gid+8)
#pragma unroll
    for (int j = 0; j < 2; j++) {
        float b = best[j];
        int ix = bi[j];
#pragma unroll
        for (int o = 1; o < 4; o <<= 1) {
            float ob = __shfl_xor_sync(0xffffffffu, b, o);
            int oi = __shfl_xor_sync(0xffffffffu, ix, o);
            if (ob < b || (ob == b && oi < ix)) { b = ob; ix = oi; }
        }
        if (tig == 0) WIN[m0 + j * 8 + gid] = ix;
    }
    __syncthreads();

    // phase 2: quantize writes + diff + ind (16 rows per warp)
    float dsum = 0.f;
    bool write_ind = (out_size >= NTOT + 1 + NROWS);
#pragma unroll 1
    for (int i = 0; i < 16; i++) {
        int r = wid * 16 + i;
        int bk = WIN[r];
        size_t n = (size_t)base_row + r;
        float2 ev = ((const float2*)(g_embT + bk * DIMK))[lane];
        float2 xv = ((const float2*)(x + n * DIMK))[lane];
        ((float2*)(out + n * DIMK))[lane] = ev;
        float dx = ev.x - xv.x, dy = ev.y - xv.y;
        dsum = fmaf(dx, dx, dsum);
        dsum = fmaf(dy, dy, dsum);
        if (lane == 0 && write_ind) out[NTOT + 1 + n] = (float)bk;
    }

    red[tid] = dsum;
    __syncthreads();
#pragma unroll
    for (int s = TPB / 2; s > 0; s >>= 1) {
        if (tid < s) red[tid] += red[tid + s];
        __syncthreads();
    }
    if (tid == 0) {
        unsigned long long q2 = (unsigned long long)((double)red[0] * 1048576.0 + 0.5);
        atomicAdd(&g_diff_acc, q2);
        __threadfence();
        unsigned t = atomicAdd(&g_ticket, 1u);
        if (t == (unsigned)(NBLK - 1)) {
            unsigned long long tot = atomicExch(&g_diff_acc, 0ull);
            atomicExch(&g_ticket, 0u);
            if (out_size >= NTOT + 1)
                out[NTOT] = (float)((double)tot * (1.0 / 1048576.0) / (double)NTOT);
        }
    }
}

extern "C" void kernel_launch(void* const* d_in, const int* in_sizes, int n_in,
                              void* d_out, int out_size) {
    const float* x = (const float*)d_in[0];
    const float* embed = (const float*)d_in[1];
    float* out = (float*)d_out;

    cudaFuncSetAttribute(vq_mma_kernel,
                         cudaFuncAttributeMaxDynamicSharedMemorySize, SM_BYTES);

    vq_prep<<<1, NCODE>>>(embed);
    vq_mma_kernel<<<NBLK, TPB, SM_BYTES>>>(x, out, out_size);
}

// round 12
// speedup vs baseline: 1.4787x; 1.0713x over previous
#include <cuda_runtime.h>
#include <cstdint>

// VQ quantize via mma.sync tf32 (3xTF32 split = fp32-grade scores).
// TPB=256 / M_TILE=128 / 2 CTAs per SM; B streamed via 32KB cp.async chunks.
// Half-block register pipeline on B fragments (LDS hidden under MMAs).
// Score arithmetic bit-identical to R8/R10/R11. Out: quantize | diff | ind.

#define DIMK 64
#define NCODE 512
#define NROWS (32 * 64 * 64)
#define NTOT (NROWS * DIMK)
#define TPB 256
#define M_TILE 128
#define NBLK (NROWS / M_TILE)   // 1024
#define CF4 2048                 // float4 per 32KB chunk (8 nc-blocks)

#define SM_B0 0                          // 32768
#define SM_B1 32768                      // 32768
#define SM_NRM 65536                     // 2048
#define SM_WIN (SM_NRM + 2048)           // 512
#define SM_RED (SM_WIN + 512)            // 1024
#define SM_BYTES (SM_RED + 1024)         // 69120

__device__ __align__(16) float4 g_Bfrag[64 * 8 * 32];   // [nc][kc][lane] = {bh0,bh1,bl0,bl1}
__device__ __align__(16) float g_embT[NCODE * DIMK];
__device__ float g_nrm[NCODE];
__device__ unsigned long long g_diff_acc;
__device__ unsigned int g_ticket;

__device__ __forceinline__ uint32_t smem_u32(const void* p) {
    uint32_t a;
    asm("{ .reg .u64 t; cvta.to.shared.u64 t, %1; cvt.u32.u64 %0, t; }" : "=r"(a) : "l"(p));
    return a;
}
__device__ __forceinline__ uint32_t tf32_hi(float f) {
    uint32_t r;
    asm("cvt.rna.tf32.f32 %0, %1;" : "=r"(r) : "f"(f));
    return r;
}
__device__ __forceinline__ void mma8(float* c, const uint32_t* a, uint32_t b0, uint32_t b1) {
    asm volatile(
        "mma.sync.aligned.m16n8k8.row.col.f32.tf32.tf32.f32 "
        "{%0,%1,%2,%3}, {%4,%5,%6,%7}, {%8,%9}, {%0,%1,%2,%3};"
        : "+f"(c[0]), "+f"(c[1]), "+f"(c[2]), "+f"(c[3])
        : "r"(a[0]), "r"(a[1]), "r"(a[2]), "r"(a[3]), "r"(b0), "r"(b1));
}
__device__ __forceinline__ void cp16(uint32_t s, const void* g) {
    asm volatile("cp.async.cg.shared.global [%0], [%1], 16;" :: "r"(s), "l"(g) : "memory");
}
#define CP_COMMIT() asm volatile("cp.async.commit_group;" ::: "memory")
#define CP_WAIT1()  asm volatile("cp.async.wait_group 1;" ::: "memory")
#define CP_WAIT0()  asm volatile("cp.async.wait_group 0;" ::: "memory")

// ---- prep: parallel across 64 blocks (was the serial 13us prologue) ----
__global__ void vq_prep(const float* __restrict__ embed) {
    int gtid = blockIdx.x * blockDim.x + threadIdx.x;   // 64*256 = 16384

    // codebook transpose + norms: one code per thread (first 512 threads)
    if (gtid < NCODE) {
        int t = gtid;
        float nr = 0.f;
        for (int d = 0; d < DIMK; d++) {
            float e = embed[d * NCODE + t];
            g_embT[t * DIMK + d] = e;
            nr = fmaf(e, e, nr);
        }
        g_nrm[t] = nr;
    }

    // one B fragment entry per thread
    int i = gtid;   // [nc][kc][lane]
    int lane = i & 31;
    int kc = (i >> 5) & 7;
    int nc = i >> 8;
    int gid = lane >> 2, tig = lane & 3;
    int n = nc * 8 + gid;
    int k0 = kc * 8 + tig;
    float v0 = -2.f * embed[k0 * NCODE + n];
    float v1 = -2.f * embed[(k0 + 4) * NCODE + n];
    uint32_t h0 = tf32_hi(v0), h1 = tf32_hi(v1);
    uint32_t l0 = tf32_hi(v0 - __uint_as_float(h0));
    uint32_t l1 = tf32_hi(v1 - __uint_as_float(h1));
    float4 f;
    f.x = __uint_as_float(h0);
    f.y = __uint_as_float(h1);
    f.z = __uint_as_float(l0);
    f.w = __uint_as_float(l1);
    g_Bfrag[i] = f;
}

__global__ __launch_bounds__(TPB, 2)
void vq_mma_kernel(const float* __restrict__ x,
                   float* __restrict__ out,
                   int out_size) {
    extern __shared__ char smem[];
    float* nsm = (float*)(smem + SM_NRM);
    int* WIN = (int*)(smem + SM_WIN);
    float* red = (float*)(smem + SM_RED);

    int tid = threadIdx.x, wid = tid >> 5, lane = tid & 31;
    int gid = lane >> 2, tig = lane & 3;
    int base_row = blockIdx.x * M_TILE;

    // kick off async load of B chunk 0 into ping
    {
        uint32_t dst = smem_u32(smem + SM_B0) + tid * 16;
        const float4* src = g_Bfrag + tid;
#pragma unroll
        for (int i = 0; i < CF4 / TPB; i++)
            cp16(dst + i * TPB * 16, src + i * TPB);
        CP_COMMIT();
    }

    for (int i = tid; i < NCODE; i += TPB) nsm[i] = g_nrm[i];

    // A fragments (tf32 hi/lo): ONE m16 tile per warp, direct from gmem.
    int m0 = wid * 16;
    uint32_t Ah[8][4], Al[8][4];
    {
        const float* xr0 = x + (size_t)(base_row + m0 + gid) * DIMK;
        const float* xr8 = xr0 + 8 * DIMK;
#pragma unroll
        for (int kc = 0; kc < 8; kc++) {
            int c0 = kc * 8 + tig;
            float f[4];
            f[0] = __ldg(xr0 + c0);
            f[1] = __ldg(xr8 + c0);
            f[2] = __ldg(xr0 + c0 + 4);
            f[3] = __ldg(xr8 + c0 + 4);
#pragma unroll
            for (int j = 0; j < 4; j++) {
                uint32_t h = tf32_hi(f[j]);
                Ah[kc][j] = h;
                Al[kc][j] = tf32_hi(f[j] - __uint_as_float(h));
            }
        }
    }

    float best[2];
    int bi[2];
    best[0] = best[1] = __int_as_float(0x7f800000);
    bi[0] = bi[1] = 0;

#pragma unroll 1
    for (int c = 0; c < 8; c++) {
        if (c < 7) {
            uint32_t dst = smem_u32(smem + ((c & 1) ? SM_B0 : SM_B1)) + tid * 16;
            const float4* src = g_Bfrag + (c + 1) * CF4 + tid;
#pragma unroll
            for (int i = 0; i < CF4 / TPB; i++)
                cp16(dst + i * TPB * 16, src + i * TPB);
            CP_COMMIT();
            CP_WAIT1();   // chunk c's group complete
        } else {
            CP_WAIT0();
        }
        __syncthreads();

        const float4* Bq = (const float4*)(smem + ((c & 1) ? SM_B1 : SM_B0));

        // half-block register pipeline: b0 = kc0-3, b1 = kc4-7
        float4 b0[4], b1[4];
#pragma unroll
        for (int j = 0; j < 4; j++) b0[j] = Bq[j * 32 + lane];

#pragma unroll 2
        for (int ncl = 0; ncl < 8; ncl++) {
            const float4* blk = Bq + ncl * 8 * 32;
            // load second half of this block (consumed after 12 MMAs)
#pragma unroll
            for (int j = 0; j < 4; j++) b1[j] = blk[(4 + j) * 32 + lane];

            // bit-identical score arithmetic (acc from 0, kc order 0..7, norm last)
            float hh[4] = {0, 0, 0, 0}, lh[4] = {0, 0, 0, 0}, hl[4] = {0, 0, 0, 0};
#pragma unroll
            for (int kc = 0; kc < 4; kc++) {
                uint32_t bh0 = __float_as_uint(b0[kc].x), bh1 = __float_as_uint(b0[kc].y);
                uint32_t bl0 = __float_as_uint(b0[kc].z), bl1 = __float_as_uint(b0[kc].w);
                mma8(hh, Ah[kc], bh0, bh1);
                mma8(lh, Al[kc], bh0, bh1);
                mma8(hl, Ah[kc], bl0, bl1);
            }
            // prefetch next block's first half (b0 reads above already issued)
            const float4* nblk = Bq + ((ncl + 1) & 7) * 8 * 32;
#pragma unroll
            for (int j = 0; j < 4; j++) b0[j] = nblk[j * 32 + lane];
#pragma unroll
            for (int kc = 4; kc < 8; kc++) {
                uint32_t bh0 = __float_as_uint(b1[kc - 4].x), bh1 = __float_as_uint(b1[kc - 4].y);
                uint32_t bl0 = __float_as_uint(b1[kc - 4].z), bl1 = __float_as_uint(b1[kc - 4].w);
                mma8(hh, Ah[kc], bh0, bh1);
                mma8(lh, Al[kc], bh0, bh1);
                mma8(hl, Ah[kc], bl0, bl1);
            }
            int n0 = (c * 8 + ncl) * 8;
            float2 nv = *(const float2*)(nsm + n0 + 2 * tig);
            int ca = n0 + 2 * tig, cb = ca + 1;
            float s;
            s = ((lh[0] + hl[0]) + hh[0]) + nv.x; if (s < best[0]) { best[0] = s; bi[0] = ca; }
            s = ((lh[1] + hl[1]) + hh[1]) + nv.y; if (s < best[0]) { best[0] = s; bi[0] = cb; }
            s = ((lh[2] + hl[2]) + hh[2]) + nv.x; if (s < best[1]) { best[1] = s; bi[1] = ca; }
            s = ((lh[3] + hl[3]) + hh[3]) + nv.y; if (s < best[1]) { best[1] = s; bi[1] = cb; }
        }
        __syncthreads();   // done reading Bq before overwrite next iter
    }

    // reduce across the 4 lanes of each quad (j=0: row gid, j=1: row gid+8)
#pragma unroll
    for (int j = 0; j < 2; j++) {
        float b = best[j];
        int ix = bi[j];
#pragma unroll
        for (int o = 1; o < 4; o <<= 1) {
            float ob = __shfl_xor_sync(0xffffffffu, b, o);
            int oi = __shfl_xor_sync(0xffffffffu, ix, o);
            if (ob < b || (ob == b && oi < ix)) { b = ob; ix = oi; }
        }
        if (tig == 0) WIN[m0 + j * 8 + gid] = ix;
    }
    __syncthreads();

    // phase 2: quantize writes + diff + ind (16 rows per warp)
    float dsum = 0.f;
    bool write_ind = (out_size >= NTOT + 1 + NROWS);
#pragma unroll 1
    for (int i = 0; i < 16; i++) {
        int r = wid * 16 + i;
        int bk = WIN[r];
        size_t n = (size_t)base_row + r;
        float2 ev = ((const float2*)(g_embT + bk * DIMK))[lane];
        float2 xv = ((const float2*)(x + n * DIMK))[lane];
        ((float2*)(out + n * DIMK))[lane] = ev;
        float dx = ev.x - xv.x, dy = ev.y - xv.y;
        dsum = fmaf(dx, dx, dsum);
        dsum = fmaf(dy, dy, dsum);
        if (lane == 0 && write_ind) out[NTOT + 1 + n] = (float)bk;
    }

    red[tid] = dsum;
    __syncthreads();
#pragma unroll
    for (int s = TPB / 2; s > 0; s >>= 1) {
        if (tid < s) red[tid] += red[tid + s];
        __syncthreads();
    }
    if (tid == 0) {
        unsigned long long q2 = (unsigned long long)((double)red[0] * 1048576.0 + 0.5);
        atomicAdd(&g_diff_acc, q2);
        __threadfence();
        unsigned t = atomicAdd(&g_ticket, 1u);
        if (t == (unsigned)(NBLK - 1)) {
            unsigned long long tot = atomicExch(&g_diff_acc, 0ull);
            atomicExch(&g_ticket, 0u);
            if (out_size >= NTOT + 1)
                out[NTOT] = (float)((double)tot * (1.0 / 1048576.0) / (double)NTOT);
        }
    }
}

extern "C" void kernel_launch(void* const* d_in, const int* in_sizes, int n_in,
                              void* d_out, int out_size) {
    const float* x = (const float*)d_in[0];
    const float* embed = (const float*)d_in[1];
    float* out = (float*)d_out;

    cudaFuncSetAttribute(vq_mma_kernel,
                         cudaFuncAttributeMaxDynamicSharedMemorySize, SM_BYTES);

    vq_prep<<<64, 256>>>(embed);
    vq_mma_kernel<<<NBLK, TPB, SM_BYTES>>>(x, out, out_size);
}